// round 5
// baseline (speedup 1.0000x reference)
#include <cuda_runtime.h>
#include <cuda_bf16.h>

// Problem constants
#define Bc 2
#define Nc 96
#define NNc 9216            // Nc*Nc
#define Dc 64
#define Hc 4
#define DKc 16
#define ROWS_TOTAL 18432    // Bc*NNc

typedef unsigned long long u64;

// ---- packed f32x2 helpers ----
#define FMA2(d, a, b, c) asm("fma.rn.f32x2 %0, %1, %2, %3;" : "=l"(d) : "l"(a), "l"(b), "l"(c))
#define MUL2(d, a, b)    asm("mul.rn.f32x2 %0, %1, %2;"     : "=l"(d) : "l"(a), "l"(b))
#define PACK2(d, lo, hi) asm("mov.b64 %0, {%1, %2};"        : "=l"(d) : "f"(lo), "f"(hi))
#define UNPACK2(lo, hi, d) asm("mov.b64 {%0, %1}, %2;"      : "=f"(lo), "=f"(hi) : "l"(d))

// Scratch (device globals; allocation-free per harness rules)
// g_proj layout: [proj(4)][b(2)][h(4)][i(9216)][d(16)]  (rk slot unused)
__device__ float g_proj[4u * Bc * Hc * NNc * DKc];          // 18.9 MB
// rk transposed: [b][h][a(96)][d(16)][y(96)]
__device__ float g_rkT[(size_t)Bc * Hc * Nc * DKc * Nc];    // 4.7 MB
__device__ float g_attout[(size_t)ROWS_TOTAL * Dc];         // 4.7 MB

// ---------------------------------------------------------------------------
// Kernel A: projection, one projection per blockIdx.y.
// 128 threads, 128 rows x 64 cols, 8x8 register tile per thread.
// proj==1 (rk) written TRANSPOSED into g_rkT.
// ---------------------------------------------------------------------------
#define A_WS_STRIDE 72

__global__ void __launch_bounds__(128)
proj_kernel(const float* __restrict__ state,
            const float* __restrict__ w_lk, const float* __restrict__ b_lk,
            const float* __restrict__ w_rk, const float* __restrict__ b_rk,
            const float* __restrict__ w_lv, const float* __restrict__ b_lv,
            const float* __restrict__ w_rv, const float* __restrict__ b_rv)
{
    __shared__ __align__(16) float w_s[64 * A_WS_STRIDE];
    __shared__ __align__(16) float st_s[128 * 64];
    __shared__ float bias_s[64];

    const int tid = threadIdx.x;
    const int rowBase = blockIdx.x * 128;
    const int proj = blockIdx.y;

    const float* W = (proj == 0) ? w_lk : (proj == 1) ? w_rk
                    : (proj == 2) ? w_lv : w_rv;
    const float* Bv = (proj == 0) ? b_lk : (proj == 1) ? b_rk
                     : (proj == 2) ? b_lv : b_rv;

    for (int idx = tid; idx < 4096; idx += 128) {
        int p = idx >> 6, k = idx & 63;
        w_s[k * A_WS_STRIDE + p] = W[idx];
    }
    if (tid < 64) bias_s[tid] = Bv[tid];
    {
        const float4* src = (const float4*)(state + (size_t)rowBase * 64);
        float4* dst = (float4*)st_s;
        for (int i = tid; i < 2048; i += 128) dst[i] = src[i];
    }
    __syncthreads();

    const int p0 = (tid & 7) * 8;    // output column group (8 wide)
    const int r0 = (tid >> 3) * 8;   // row group (8 rows)

    float acc[8][8];
#pragma unroll
    for (int i = 0; i < 8; ++i)
#pragma unroll
        for (int j = 0; j < 8; ++j) acc[i][j] = 0.f;

#pragma unroll 2
    for (int k = 0; k < 64; ++k) {
        float4 wa = *(const float4*)&w_s[k * A_WS_STRIDE + p0];
        float4 wb = *(const float4*)&w_s[k * A_WS_STRIDE + p0 + 4];
        float sv[8];
#pragma unroll
        for (int i = 0; i < 8; ++i) sv[i] = st_s[(r0 + i) * 64 + k];
#pragma unroll
        for (int i = 0; i < 8; ++i) {
            acc[i][0] += sv[i] * wa.x;
            acc[i][1] += sv[i] * wa.y;
            acc[i][2] += sv[i] * wa.z;
            acc[i][3] += sv[i] * wa.w;
            acc[i][4] += sv[i] * wb.x;
            acc[i][5] += sv[i] * wb.y;
            acc[i][6] += sv[i] * wb.z;
            acc[i][7] += sv[i] * wb.w;
        }
    }

    const float4 ba = *(const float4*)&bias_s[p0];
    const float4 bb = *(const float4*)&bias_s[p0 + 4];
    const int h  = p0 >> 4;
    const int d0 = p0 & 15;

#pragma unroll
    for (int i = 0; i < 8; ++i) {
        int row = rowBase + r0 + i;
        int b   = row / NNc;
        int idx = row - b * NNc;
        float v[8];
        v[0] = acc[i][0] + ba.x; v[1] = acc[i][1] + ba.y;
        v[2] = acc[i][2] + ba.z; v[3] = acc[i][3] + ba.w;
        v[4] = acc[i][4] + bb.x; v[5] = acc[i][5] + bb.y;
        v[6] = acc[i][6] + bb.z; v[7] = acc[i][7] + bb.w;
        if (proj == 1) {
            int a = idx / 96, y = idx - a * 96;
            size_t base = ((((size_t)(b * Hc + h) * Nc + a) * DKc + d0) * Nc) + y;
#pragma unroll
            for (int j = 0; j < 8; ++j) g_rkT[base + (size_t)j * 96] = v[j];
        } else {
            size_t off = ((size_t)((proj * Bc + b) * Hc + h) * NNc + idx) * DKc + d0;
            *(float4*)&g_proj[off]     = make_float4(v[0], v[1], v[2], v[3]);
            *(float4*)&g_proj[off + 4] = make_float4(v[4], v[5], v[6], v[7]);
        }
    }
}

// ---------------------------------------------------------------------------
// Kernel B: scores + softmax(a) + triple-product contraction.
// Block per (b, h, x-tile of 3).  y in thirds of 32.
// Phase 2/3 use packed f32x2 FMA along d; softmax parallel 4 threads/col.
// smem = 75.3 KB -> 3 blocks/SM, grid 256 -> single resident wave.
// ---------------------------------------------------------------------------
#define TXc 3
#define YHc 32
#define SCA 33                 // sc stride per a (padded)
#define SCTX (96 * SCA)        // 3168

__global__ void __launch_bounds__(384, 3)
attn_kernel()
{
    extern __shared__ __align__(16) float smem[];
    float* lk_s = smem;                 // 4608 (overlaid by partials in ph.3)
    float* lv_s = smem + 4608;          // 4608
    float* sc   = smem + 9216;          // 3 * 3168 = 9504
    float* linv = smem + 18720;         // 96
    float* part = lk_s;                 // overlay: 9 * 128 float4 = 4608 floats

    const int tid = threadIdx.x;
    const int xt = blockIdx.x % (Nc / TXc);
    const int bh = blockIdx.x / (Nc / TXc);
    const int h  = bh % Hc;
    const int b  = bh / Hc;
    const int x0 = xt * TXc;

    const int slab = NNc * DKc;  // 147456
    const float* lkbase = g_proj + (size_t)((0 * Bc + b) * Hc + h) * slab;
    const float* lvbase = g_proj + (size_t)((2 * Bc + b) * Hc + h) * slab;
    const float* rvbase = g_proj + (size_t)((3 * Bc + b) * Hc + h) * slab;
    const float* rkT    = g_rkT + (size_t)(b * Hc + h) * Nc * DKc * Nc;

    // load lv once (lives for whole kernel)
    {
        const float4* slv = (const float4*)(lvbase + (size_t)x0 * 1536);
        float4* dlv = (float4*)lv_s;
        for (int i = tid; i < 1152; i += 384) dlv[i] = slv[i];
    }

    for (int yh = 0; yh < 96; yh += YHc) {
        // (re)load lk (its smem is reused for partials each iteration)
        {
            const float4* slk = (const float4*)(lkbase + (size_t)x0 * 1536);
            float4* dlk = (float4*)lk_s;
            for (int i = tid; i < 1152; i += 384) dlk[i] = slk[i];
        }
        __syncthreads();

        // ---- Phase 2: lanes = y, warps stride over a; f32x2 dot along d.
        {
            const int yl = tid & 31;
            const int w  = tid >> 5;          // 12 warps
#pragma unroll
            for (int ai = 0; ai < 8; ++ai) {
                const int a = w + ai * 12;
                const float* rkp = rkT + (size_t)(a * 16) * 96 + yh + yl;
                float r[16];
#pragma unroll
                for (int d = 0; d < 16; ++d) r[d] = rkp[(size_t)d * 96];
                u64 rp[8];
#pragma unroll
                for (int j = 0; j < 8; ++j) PACK2(rp[j], r[2 * j], r[2 * j + 1]);
#pragma unroll
                for (int tx = 0; tx < TXc; ++tx) {
                    const ulonglong2* lp = (const ulonglong2*)(lk_s + tx * 1536 + a * 16);
                    ulonglong2 l0 = lp[0], l1 = lp[1], l2 = lp[2], l3 = lp[3];
                    u64 t;
                    MUL2(t, l0.x, rp[0]);
                    FMA2(t, l0.y, rp[1], t);
                    FMA2(t, l1.x, rp[2], t);
                    FMA2(t, l1.y, rp[3], t);
                    FMA2(t, l2.x, rp[4], t);
                    FMA2(t, l2.y, rp[5], t);
                    FMA2(t, l3.x, rp[6], t);
                    FMA2(t, l3.y, rp[7], t);
                    float lo, hi;
                    UNPACK2(lo, hi, t);
                    sc[tx * SCTX + a * SCA + yl] = (lo + hi) * 0.25f;
                }
            }
        }
        __syncthreads();

        // ---- Softmax over a: 4 threads per column + shfl reduce.
        {
            const int col = tid >> 2;         // 0..95
            const int sub = tid & 3;
            const int tx  = col >> 5;
            const int yl  = col & 31;
            float* base = sc + tx * SCTX + yl;
            float m = -1e30f;
#pragma unroll 4
            for (int a = sub; a < 96; a += 4) m = fmaxf(m, base[a * SCA]);
            m = fmaxf(m, __shfl_xor_sync(0xffffffffu, m, 1));
            m = fmaxf(m, __shfl_xor_sync(0xffffffffu, m, 2));
            float l = 0.f;
#pragma unroll 4
            for (int a = sub; a < 96; a += 4) {
                float e = __expf(base[a * SCA] - m);
                base[a * SCA] = e;
                l += e;
            }
            l += __shfl_xor_sync(0xffffffffu, l, 1);
            l += __shfl_xor_sync(0xffffffffu, l, 2);
            if (sub == 0) linv[col] = 1.f / l;
        }
        __syncthreads();

        // ---- Phase 3: a-split, f32x2 along d; rv loaded once per (a,y,d)
        {
            const int dq = tid & 3;
            const int yl = (tid >> 2) & 31;
            const int as = tid >> 7;          // 0..2: a-chunk
            const int y  = yh + yl;
            u64 a0x = 0ull, a0y = 0ull, a1x = 0ull, a1y = 0ull, a2x = 0ull, a2y = 0ull;
            const int aEnd = as * 32 + 32;
#pragma unroll 4
            for (int a = as * 32; a < aEnd; ++a) {
                ulonglong2 rv = *(const ulonglong2*)(rvbase + (size_t)(a * 96 + y) * 16 + dq * 4);
                float w0 = sc[0 * SCTX + a * SCA + yl];
                float w1 = sc[1 * SCTX + a * SCA + yl];
                float w2 = sc[2 * SCTX + a * SCA + yl];
                u64 wp0, wp1, wp2;
                PACK2(wp0, w0, w0);
                PACK2(wp1, w1, w1);
                PACK2(wp2, w2, w2);
                ulonglong2 v0 = *(const ulonglong2*)(lv_s + 0 * 1536 + a * 16 + dq * 4);
                ulonglong2 v1 = *(const ulonglong2*)(lv_s + 1 * 1536 + a * 16 + dq * 4);
                ulonglong2 v2 = *(const ulonglong2*)(lv_s + 2 * 1536 + a * 16 + dq * 4);
                u64 t;
                MUL2(t, v0.x, rv.x); FMA2(a0x, wp0, t, a0x);
                MUL2(t, v0.y, rv.y); FMA2(a0y, wp0, t, a0y);
                MUL2(t, v1.x, rv.x); FMA2(a1x, wp1, t, a1x);
                MUL2(t, v1.y, rv.y); FMA2(a1y, wp1, t, a1y);
                MUL2(t, v2.x, rv.x); FMA2(a2x, wp2, t, a2x);
                MUL2(t, v2.y, rv.y); FMA2(a2y, wp2, t, a2y);
            }
            float4 f0, f1, f2;
            UNPACK2(f0.x, f0.y, a0x); UNPACK2(f0.z, f0.w, a0y);
            UNPACK2(f1.x, f1.y, a1x); UNPACK2(f1.z, f1.w, a1y);
            UNPACK2(f2.x, f2.y, a2x); UNPACK2(f2.z, f2.w, a2y);
            float4* p4 = (float4*)part;
            p4[(as * 3 + 0) * 128 + yl * 4 + dq] = f0;
            p4[(as * 3 + 1) * 128 + yl * 4 + dq] = f1;
            p4[(as * 3 + 2) * 128 + yl * 4 + dq] = f2;
        }
        __syncthreads();

        // ---- Reduce partials and store
        {
            const int tx = tid >> 7;          // 0..2
            const int rr = tid & 127;         // yl*4 + dq
            const int yl = rr >> 2;
            const int dq = rr & 3;
            const float4* p4 = (const float4*)part;
            float4 s0 = p4[(0 * 3 + tx) * 128 + rr];
            float4 s1 = p4[(1 * 3 + tx) * 128 + rr];
            float4 s2 = p4[(2 * 3 + tx) * 128 + rr];
            float sl = linv[tx * 32 + yl];
            float4 o;
            o.x = (s0.x + s1.x + s2.x) * sl;
            o.y = (s0.y + s1.y + s2.y) * sl;
            o.z = (s0.z + s1.z + s2.z) * sl;
            o.w = (s0.w + s1.w + s2.w) * sl;
            size_t row = (size_t)b * NNc + (size_t)(x0 + tx) * 96 + (yh + yl);
            *(float4*)&g_attout[row * 64 + h * 16 + dq * 4] = o;
        }
        __syncthreads();
    }
}

// ---------------------------------------------------------------------------
// Kernel C: output projection, same 8x8 register-tile structure.
// ---------------------------------------------------------------------------
__global__ void __launch_bounds__(128)
out_kernel(const float* __restrict__ w_out, const float* __restrict__ b_out,
           float* __restrict__ out)
{
    __shared__ __align__(16) float w_s[64 * A_WS_STRIDE];
    __shared__ __align__(16) float st_s[128 * 64];
    __shared__ float bias_s[64];

    const int tid = threadIdx.x;
    const int rowBase = blockIdx.x * 128;

    for (int idx = tid; idx < 4096; idx += 128) {
        int p = idx >> 6, k = idx & 63;
        w_s[k * A_WS_STRIDE + p] = w_out[idx];
    }
    if (tid < 64) bias_s[tid] = b_out[tid];
    {
        const float4* src = (const float4*)(g_attout + (size_t)rowBase * 64);
        float4* dst = (float4*)st_s;
        for (int i = tid; i < 2048; i += 128) dst[i] = src[i];
    }
    __syncthreads();

    const int p0 = (tid & 7) * 8;
    const int r0 = (tid >> 3) * 8;

    float acc[8][8];
#pragma unroll
    for (int i = 0; i < 8; ++i)
#pragma unroll
        for (int j = 0; j < 8; ++j) acc[i][j] = 0.f;

#pragma unroll 2
    for (int k = 0; k < 64; ++k) {
        float4 wa = *(const float4*)&w_s[k * A_WS_STRIDE + p0];
        float4 wb = *(const float4*)&w_s[k * A_WS_STRIDE + p0 + 4];
        float sv[8];
#pragma unroll
        for (int i = 0; i < 8; ++i) sv[i] = st_s[(r0 + i) * 64 + k];
#pragma unroll
        for (int i = 0; i < 8; ++i) {
            acc[i][0] += sv[i] * wa.x;
            acc[i][1] += sv[i] * wa.y;
            acc[i][2] += sv[i] * wa.z;
            acc[i][3] += sv[i] * wa.w;
            acc[i][4] += sv[i] * wb.x;
            acc[i][5] += sv[i] * wb.y;
            acc[i][6] += sv[i] * wb.z;
            acc[i][7] += sv[i] * wb.w;
        }
    }

    const float4 ba = *(const float4*)&bias_s[p0];
    const float4 bb = *(const float4*)&bias_s[p0 + 4];

#pragma unroll
    for (int i = 0; i < 8; ++i) {
        int row = rowBase + r0 + i;
        float4 va = make_float4(acc[i][0] + ba.x, acc[i][1] + ba.y,
                                acc[i][2] + ba.z, acc[i][3] + ba.w);
        float4 vb = make_float4(acc[i][4] + bb.x, acc[i][5] + bb.y,
                                acc[i][6] + bb.z, acc[i][7] + bb.w);
        *(float4*)&out[(size_t)row * 64 + p0]     = va;
        *(float4*)&out[(size_t)row * 64 + p0 + 4] = vb;
    }
}

// ---------------------------------------------------------------------------
extern "C" void kernel_launch(void* const* d_in, const int* in_sizes, int n_in,
                              void* d_out, int out_size)
{
    const float* state = (const float*)d_in[0];
    const float* w_lk = (const float*)d_in[1];
    const float* b_lk = (const float*)d_in[2];
    const float* w_rk = (const float*)d_in[3];
    const float* b_rk = (const float*)d_in[4];
    const float* w_lv = (const float*)d_in[5];
    const float* b_lv = (const float*)d_in[6];
    const float* w_rv = (const float*)d_in[7];
    const float* b_rv = (const float*)d_in[8];
    const float* w_out = (const float*)d_in[9];
    const float* b_out = (const float*)d_in[10];
    float* out = (float*)d_out;

    const int smemB = (4608 + 4608 + 9504 + 96) * 4;  // 75264 B

    static bool attr_done = false;
    if (!attr_done) {
        cudaFuncSetAttribute(attn_kernel,
                             cudaFuncAttributeMaxDynamicSharedMemorySize, smemB);
        attr_done = true;
    }

    dim3 gridA(ROWS_TOTAL / 128, 4);
    proj_kernel<<<gridA, 128>>>(
        state, w_lk, b_lk, w_rk, b_rk, w_lv, b_lv, w_rv, b_rv);

    attn_kernel<<<Bc * Hc * (Nc / TXc), 384, smemB>>>();

    out_kernel<<<ROWS_TOTAL / 128, 128>>>(w_out, b_out, out);
}

// round 6
// speedup vs baseline: 1.1124x; 1.1124x over previous
#include <cuda_runtime.h>
#include <cuda_bf16.h>

// Problem constants
#define Bc 2
#define Nc 96
#define NNc 9216            // Nc*Nc
#define Dc 64
#define Hc 4
#define DKc 16
#define ROWS_TOTAL 18432    // Bc*NNc

// Scratch (device globals; allocation-free per harness rules)
// g_proj layout: [proj(4)][b(2)][h(4)][i(9216)][d(16)]  (rk slot unused)
__device__ float g_proj[4u * Bc * Hc * NNc * DKc];          // 18.9 MB
// rk transposed: [b][h][a(96)][d(16)][y(96)]
__device__ float g_rkT[(size_t)Bc * Hc * Nc * DKc * Nc];    // 4.7 MB
__device__ float g_attout[(size_t)ROWS_TOTAL * Dc];         // 4.7 MB

// ---------------------------------------------------------------------------
// Kernel A: projection, one projection per blockIdx.y.
// Block: 256 threads, 64 rows x 64 cols, 4x4 tile, k-vectorized state loads.
// proj==1 (rk) written TRANSPOSED into g_rkT.
// ---------------------------------------------------------------------------
#define A_WS_STRIDE 68
#define ST_STRIDE 68

__global__ void __launch_bounds__(256)
proj_kernel(const float* __restrict__ state,
            const float* __restrict__ w_lk, const float* __restrict__ b_lk,
            const float* __restrict__ w_rk, const float* __restrict__ b_rk,
            const float* __restrict__ w_lv, const float* __restrict__ b_lv,
            const float* __restrict__ w_rv, const float* __restrict__ b_rv)
{
    __shared__ __align__(16) float w_s[64 * A_WS_STRIDE];
    __shared__ __align__(16) float st_s[64 * ST_STRIDE];
    __shared__ float bias_s[64];

    const int tid = threadIdx.x;
    const int rowBase = blockIdx.x * 64;
    const int proj = blockIdx.y;

    const float* W = (proj == 0) ? w_lk : (proj == 1) ? w_rk
                    : (proj == 2) ? w_lv : w_rv;
    const float* Bv = (proj == 0) ? b_lk : (proj == 1) ? b_rk
                     : (proj == 2) ? b_lv : b_rv;

    // Weights transposed: w_s[k][p] = W[p][k]
    for (int idx = tid; idx < 4096; idx += 256) {
        int p = idx >> 6, k = idx & 63;
        w_s[k * A_WS_STRIDE + p] = W[idx];
    }
    if (tid < 64) bias_s[tid] = Bv[tid];
    // State tile, padded row stride (keeps float4 alignment, kills bank dup)
    {
        int r = tid >> 2;          // 64 rows, 4 threads per row
        int c = (tid & 3) * 16;    // 16 floats each
        const float4* src = (const float4*)(state + (size_t)(rowBase + r) * 64 + c);
        float4* dst = (float4*)&st_s[r * ST_STRIDE + c];
        dst[0] = src[0]; dst[1] = src[1]; dst[2] = src[2]; dst[3] = src[3];
    }
    __syncthreads();

    const int p0 = (tid & 15) * 4;   // output column group
    const int r0 = (tid >> 4) * 4;   // row group

    float acc[4][4];
#pragma unroll
    for (int i = 0; i < 4; ++i)
#pragma unroll
        for (int j = 0; j < 4; ++j) acc[i][j] = 0.f;

#pragma unroll 4
    for (int k4 = 0; k4 < 64; k4 += 4) {
        float4 sv[4];
#pragma unroll
        for (int i = 0; i < 4; ++i)
            sv[i] = *(const float4*)&st_s[(r0 + i) * ST_STRIDE + k4];
#pragma unroll
        for (int kk = 0; kk < 4; ++kk) {
            float4 wv = *(const float4*)&w_s[(k4 + kk) * A_WS_STRIDE + p0];
#pragma unroll
            for (int i = 0; i < 4; ++i) {
                float s = (kk == 0) ? sv[i].x : (kk == 1) ? sv[i].y
                         : (kk == 2) ? sv[i].z : sv[i].w;
                acc[i][0] += s * wv.x;
                acc[i][1] += s * wv.y;
                acc[i][2] += s * wv.z;
                acc[i][3] += s * wv.w;
            }
        }
    }

    const float4 bv = *(const float4*)&bias_s[p0];
    const int h  = p0 >> 4;
    const int d0 = p0 & 15;

#pragma unroll
    for (int i = 0; i < 4; ++i) {
        int row = rowBase + r0 + i;
        int b   = row / NNc;
        int idx = row - b * NNc;
        float v0 = acc[i][0] + bv.x;
        float v1 = acc[i][1] + bv.y;
        float v2 = acc[i][2] + bv.z;
        float v3 = acc[i][3] + bv.w;
        if (proj == 1) {
            // transposed: g_rkT[b][h][a][d][y]
            int a = idx / 96, y = idx - a * 96;
            size_t base = ((((size_t)(b * Hc + h) * Nc + a) * DKc + d0) * Nc) + y;
            g_rkT[base]          = v0;
            g_rkT[base + 96]     = v1;
            g_rkT[base + 192]    = v2;
            g_rkT[base + 288]    = v3;
        } else {
            size_t off = ((size_t)((proj * Bc + b) * Hc + h) * NNc + idx) * DKc + d0;
            float4 v; v.x = v0; v.y = v1; v.z = v2; v.w = v3;
            *(float4*)&g_proj[off] = v;
        }
    }
}

// ---------------------------------------------------------------------------
// Kernel B: scores + softmax(a) + triple-product contraction.  (R4, proven)
// Block per (b, h, x-tile of 3).  y in thirds of 32.
// smem = 74.1 KB -> 3 blocks/SM, grid 256 -> single resident wave.
// ---------------------------------------------------------------------------
#define TXc 3
#define YHc 32

__global__ void __launch_bounds__(384, 3)
attn_kernel()
{
    extern __shared__ __align__(16) float smem[];
    float* lk_s = smem;                 // 4608 (overlaid by partials in ph.3)
    float* lv_s = smem + 4608;          // 4608
    float* sc   = smem + 9216;          // TX * 96 * 32 = 9216
    float* linv = smem + 18432;         // 96
    float* part = lk_s;                 // overlay: 9 * 128 float4 = 4608 floats

    const int tid = threadIdx.x;
    const int xt = blockIdx.x % (Nc / TXc);
    const int bh = blockIdx.x / (Nc / TXc);
    const int h  = bh % Hc;
    const int b  = bh / Hc;
    const int x0 = xt * TXc;

    const int slab = NNc * DKc;  // 147456
    const float* lkbase = g_proj + (size_t)((0 * Bc + b) * Hc + h) * slab;
    const float* lvbase = g_proj + (size_t)((2 * Bc + b) * Hc + h) * slab;
    const float* rvbase = g_proj + (size_t)((3 * Bc + b) * Hc + h) * slab;
    const float* rkT    = g_rkT + (size_t)(b * Hc + h) * Nc * DKc * Nc;

    // load lv once (lives for whole kernel)
    {
        const float4* slv = (const float4*)(lvbase + (size_t)x0 * 1536);
        float4* dlv = (float4*)lv_s;
        for (int i = tid; i < 1152; i += 384) dlv[i] = slv[i];
    }

    for (int yh = 0; yh < 96; yh += YHc) {
        // (re)load lk (its smem is reused for partials each iteration)
        {
            const float4* slk = (const float4*)(lkbase + (size_t)x0 * 1536);
            float4* dlk = (float4*)lk_s;
            for (int i = tid; i < 1152; i += 384) dlk[i] = slk[i];
        }
        __syncthreads();

        // ---- Phase 2: lanes = y, warps stride over a. rk column in regs.
        {
            const int yl = tid & 31;
            const int w  = tid >> 5;          // 12 warps
            for (int a = w; a < 96; a += 12) {
                const float* rkp = rkT + (size_t)(a * 16) * 96 + yh + yl;
                float r[16];
#pragma unroll
                for (int d = 0; d < 16; ++d) r[d] = rkp[(size_t)d * 96];
#pragma unroll
                for (int tx = 0; tx < TXc; ++tx) {
                    const float4* lp = (const float4*)(lk_s + tx * 1536 + a * 16);
                    float4 l0 = lp[0], l1 = lp[1], l2 = lp[2], l3 = lp[3];
                    float s0 = l0.x * r[0]  + l0.y * r[1]  + l0.z * r[2]  + l0.w * r[3];
                    float s1 = l1.x * r[4]  + l1.y * r[5]  + l1.z * r[6]  + l1.w * r[7];
                    float s2 = l2.x * r[8]  + l2.y * r[9]  + l2.z * r[10] + l2.w * r[11];
                    float s3 = l3.x * r[12] + l3.y * r[13] + l3.z * r[14] + l3.w * r[15];
                    sc[tx * 3072 + a * 32 + yl] = (s0 + s1 + s2 + s3) * 0.25f;
                }
            }
        }
        __syncthreads();

        // ---- Softmax over a (unnormalized exp; keep 1/sum)
        if (tid < TXc * YHc) {
            int tx = tid >> 5;
            int yl = tid & 31;
            float* col = sc + tx * 3072 + yl;
            float m = -1e30f;
#pragma unroll 4
            for (int a = 0; a < 96; ++a) m = fmaxf(m, col[a * 32]);
            float l = 0.f;
#pragma unroll 4
            for (int a = 0; a < 96; ++a) {
                float e = __expf(col[a * 32] - m);
                col[a * 32] = e;
                l += e;
            }
            linv[tid] = 1.f / l;
        }
        __syncthreads();

        // ---- Phase 3: a-split accumulation, rv loaded once per (a,y,d)
        {
            const int dq = tid & 3;
            const int yl = (tid >> 2) & 31;
            const int as = tid >> 7;          // 0..2: a-chunk
            const int y  = yh + yl;
            float4 acc0 = {0,0,0,0}, acc1 = {0,0,0,0}, acc2 = {0,0,0,0};
            const int aEnd = as * 32 + 32;
#pragma unroll 4
            for (int a = as * 32; a < aEnd; ++a) {
                float4 rv = *(const float4*)(rvbase + (size_t)(a * 96 + y) * 16 + dq * 4);
                float w0 = sc[0 * 3072 + a * 32 + yl];
                float w1 = sc[1 * 3072 + a * 32 + yl];
                float w2 = sc[2 * 3072 + a * 32 + yl];
                float4 v0 = *(const float4*)(lv_s + 0 * 1536 + a * 16 + dq * 4);
                float4 v1 = *(const float4*)(lv_s + 1 * 1536 + a * 16 + dq * 4);
                float4 v2 = *(const float4*)(lv_s + 2 * 1536 + a * 16 + dq * 4);
                acc0.x += w0 * (v0.x * rv.x);  acc0.y += w0 * (v0.y * rv.y);
                acc0.z += w0 * (v0.z * rv.z);  acc0.w += w0 * (v0.w * rv.w);
                acc1.x += w1 * (v1.x * rv.x);  acc1.y += w1 * (v1.y * rv.y);
                acc1.z += w1 * (v1.z * rv.z);  acc1.w += w1 * (v1.w * rv.w);
                acc2.x += w2 * (v2.x * rv.x);  acc2.y += w2 * (v2.y * rv.y);
                acc2.z += w2 * (v2.z * rv.z);  acc2.w += w2 * (v2.w * rv.w);
            }
            float4* p4 = (float4*)part;
            p4[(as * 3 + 0) * 128 + yl * 4 + dq] = acc0;
            p4[(as * 3 + 1) * 128 + yl * 4 + dq] = acc1;
            p4[(as * 3 + 2) * 128 + yl * 4 + dq] = acc2;
        }
        __syncthreads();

        // ---- Reduce partials and store
        {
            const int tx = tid >> 7;          // 0..2
            const int rr = tid & 127;         // yl*4 + dq
            const int yl = rr >> 2;
            const int dq = rr & 3;
            const float4* p4 = (const float4*)part;
            float4 s0 = p4[(0 * 3 + tx) * 128 + rr];
            float4 s1 = p4[(1 * 3 + tx) * 128 + rr];
            float4 s2 = p4[(2 * 3 + tx) * 128 + rr];
            float sl = linv[tx * 32 + yl];
            float4 o;
            o.x = (s0.x + s1.x + s2.x) * sl;
            o.y = (s0.y + s1.y + s2.y) * sl;
            o.z = (s0.z + s1.z + s2.z) * sl;
            o.w = (s0.w + s1.w + s2.w) * sl;
            size_t row = (size_t)b * NNc + (size_t)(x0 + tx) * 96 + (yh + yl);
            *(float4*)&g_attout[row * 64 + h * 16 + dq * 4] = o;
        }
        __syncthreads();
    }
}

// ---------------------------------------------------------------------------
// Kernel C: output projection, same k-vectorized 4x4 structure as proj.
// ---------------------------------------------------------------------------
__global__ void __launch_bounds__(256)
out_kernel(const float* __restrict__ w_out, const float* __restrict__ b_out,
           float* __restrict__ out)
{
    __shared__ __align__(16) float w_s[64 * A_WS_STRIDE];
    __shared__ __align__(16) float st_s[64 * ST_STRIDE];
    __shared__ float bias_s[64];

    const int tid = threadIdx.x;
    const int rowBase = blockIdx.x * 64;

    for (int idx = tid; idx < 4096; idx += 256) {
        int p = idx >> 6, k = idx & 63;
        w_s[k * A_WS_STRIDE + p] = w_out[idx];
    }
    if (tid < 64) bias_s[tid] = b_out[tid];
    {
        int r = tid >> 2;
        int c = (tid & 3) * 16;
        const float4* src = (const float4*)(g_attout + (size_t)(rowBase + r) * 64 + c);
        float4* dst = (float4*)&st_s[r * ST_STRIDE + c];
        dst[0] = src[0]; dst[1] = src[1]; dst[2] = src[2]; dst[3] = src[3];
    }
    __syncthreads();

    const int p0 = (tid & 15) * 4;
    const int r0 = (tid >> 4) * 4;

    float acc[4][4];
#pragma unroll
    for (int i = 0; i < 4; ++i)
#pragma unroll
        for (int j = 0; j < 4; ++j) acc[i][j] = 0.f;

#pragma unroll 4
    for (int k4 = 0; k4 < 64; k4 += 4) {
        float4 sv[4];
#pragma unroll
        for (int i = 0; i < 4; ++i)
            sv[i] = *(const float4*)&st_s[(r0 + i) * ST_STRIDE + k4];
#pragma unroll
        for (int kk = 0; kk < 4; ++kk) {
            float4 wv = *(const float4*)&w_s[(k4 + kk) * A_WS_STRIDE + p0];
#pragma unroll
            for (int i = 0; i < 4; ++i) {
                float s = (kk == 0) ? sv[i].x : (kk == 1) ? sv[i].y
                         : (kk == 2) ? sv[i].z : sv[i].w;
                acc[i][0] += s * wv.x;
                acc[i][1] += s * wv.y;
                acc[i][2] += s * wv.z;
                acc[i][3] += s * wv.w;
            }
        }
    }

    const float4 bv = *(const float4*)&bias_s[p0];
#pragma unroll
    for (int i = 0; i < 4; ++i) {
        int row = rowBase + r0 + i;
        float4 v;
        v.x = acc[i][0] + bv.x;
        v.y = acc[i][1] + bv.y;
        v.z = acc[i][2] + bv.z;
        v.w = acc[i][3] + bv.w;
        *(float4*)&out[(size_t)row * 64 + p0] = v;
    }
}

// ---------------------------------------------------------------------------
extern "C" void kernel_launch(void* const* d_in, const int* in_sizes, int n_in,
                              void* d_out, int out_size)
{
    const float* state = (const float*)d_in[0];
    const float* w_lk = (const float*)d_in[1];
    const float* b_lk = (const float*)d_in[2];
    const float* w_rk = (const float*)d_in[3];
    const float* b_rk = (const float*)d_in[4];
    const float* w_lv = (const float*)d_in[5];
    const float* b_lv = (const float*)d_in[6];
    const float* w_rv = (const float*)d_in[7];
    const float* b_rv = (const float*)d_in[8];
    const float* w_out = (const float*)d_in[9];
    const float* b_out = (const float*)d_in[10];
    float* out = (float*)d_out;

    const int smemB = (4608 + 4608 + 9216 + 96) * 4;  // 74112 B

    static bool attr_done = false;
    if (!attr_done) {
        cudaFuncSetAttribute(attn_kernel,
                             cudaFuncAttributeMaxDynamicSharedMemorySize, smemB);
        attr_done = true;
    }

    dim3 gridA(ROWS_TOTAL / 64, 4);
    proj_kernel<<<gridA, 256>>>(
        state, w_lk, b_lk, w_rk, b_rk, w_lv, b_lv, w_rv, b_rv);

    attn_kernel<<<Bc * Hc * (Nc / TXc), 384, smemB>>>();

    out_kernel<<<ROWS_TOTAL / 64, 256>>>(w_out, b_out, out);
}

// round 7
// speedup vs baseline: 1.2255x; 1.1016x over previous
#include <cuda_runtime.h>
#include <cuda_bf16.h>

// Problem constants
#define Bc 2
#define Nc 96
#define NNc 9216            // Nc*Nc
#define Dc 64
#define Hc 4
#define DKc 16
#define ROWS_TOTAL 18432    // Bc*NNc

// Scratch (device globals; allocation-free per harness rules)
// g_proj layout: [proj(4)][b(2)][h(4)][i(9216)][d(16)]  (rk slot unused)
__device__ float g_proj[4u * Bc * Hc * NNc * DKc];          // 18.9 MB
// rk transposed: [b][h][a(96)][d(16)][y(96)]
__device__ float g_rkT[(size_t)Bc * Hc * Nc * DKc * Nc];    // 4.7 MB
__device__ float g_attout[(size_t)ROWS_TOTAL * Dc];         // 4.7 MB

// ---------------------------------------------------------------------------
// Kernel A: projection (R3/R6 proven shape).  proj==1 -> g_rkT transposed.
// ---------------------------------------------------------------------------
#define A_WS_STRIDE 68

__global__ void __launch_bounds__(256)
proj_kernel(const float* __restrict__ state,
            const float* __restrict__ w_lk, const float* __restrict__ b_lk,
            const float* __restrict__ w_rk, const float* __restrict__ b_rk,
            const float* __restrict__ w_lv, const float* __restrict__ b_lv,
            const float* __restrict__ w_rv, const float* __restrict__ b_rv)
{
    __shared__ __align__(16) float w_s[64 * A_WS_STRIDE];
    __shared__ __align__(16) float st_s[64 * 64];
    __shared__ float bias_s[64];

    const int tid = threadIdx.x;
    const int rowBase = blockIdx.x * 64;
    const int proj = blockIdx.y;

    const float* W = (proj == 0) ? w_lk : (proj == 1) ? w_rk
                    : (proj == 2) ? w_lv : w_rv;
    const float* Bv = (proj == 0) ? b_lk : (proj == 1) ? b_rk
                     : (proj == 2) ? b_lv : b_rv;

    for (int idx = tid; idx < 4096; idx += 256) {
        int p = idx >> 6, k = idx & 63;
        w_s[k * A_WS_STRIDE + p] = W[idx];
    }
    if (tid < 64) bias_s[tid] = Bv[tid];
    {
        const float4* src = (const float4*)(state + (size_t)rowBase * 64);
        float4* dst = (float4*)st_s;
        for (int i = tid; i < 1024; i += 256) dst[i] = src[i];
    }
    __syncthreads();

    const int p0 = (tid & 15) * 4;
    const int r0 = (tid >> 4) * 4;

    float acc[4][4];
#pragma unroll
    for (int i = 0; i < 4; ++i)
#pragma unroll
        for (int j = 0; j < 4; ++j) acc[i][j] = 0.f;

#pragma unroll 8
    for (int k = 0; k < 64; ++k) {
        float4 wv = *(const float4*)&w_s[k * A_WS_STRIDE + p0];
#pragma unroll
        for (int i = 0; i < 4; ++i) {
            float s = st_s[(r0 + i) * 64 + k];
            acc[i][0] += s * wv.x;
            acc[i][1] += s * wv.y;
            acc[i][2] += s * wv.z;
            acc[i][3] += s * wv.w;
        }
    }

    const float4 bv = *(const float4*)&bias_s[p0];
    const int h  = p0 >> 4;
    const int d0 = p0 & 15;

#pragma unroll
    for (int i = 0; i < 4; ++i) {
        int row = rowBase + r0 + i;
        int b   = row / NNc;
        int idx = row - b * NNc;
        float v0 = acc[i][0] + bv.x;
        float v1 = acc[i][1] + bv.y;
        float v2 = acc[i][2] + bv.z;
        float v3 = acc[i][3] + bv.w;
        if (proj == 1) {
            int a = idx / 96, y = idx - a * 96;
            size_t base = ((((size_t)(b * Hc + h) * Nc + a) * DKc + d0) * Nc) + y;
            g_rkT[base]       = v0;
            g_rkT[base + 96]  = v1;
            g_rkT[base + 192] = v2;
            g_rkT[base + 288] = v3;
        } else {
            size_t off = ((size_t)((proj * Bc + b) * Hc + h) * NNc + idx) * DKc + d0;
            float4 v; v.x = v0; v.y = v1; v.z = v2; v.w = v3;
            *(float4*)&g_proj[off] = v;
        }
    }
}

// ---------------------------------------------------------------------------
// Kernel B: streaming edge-attention, no-max softmax (scores are tiny:
// |s| <~ 0.2, exp safe; result identical after normalization).
// Block = (b, h, x-tile of 6, y-tile of 32).  a processed in chunks of 12.
// num/den accumulators live in registers; smem only holds one a-chunk of
// lk/lv and the score chunk (18.4 KB -> 4 blocks/SM, grid 384 = one wave).
// ---------------------------------------------------------------------------
#define TXB 6
#define YB  32
#define ACH 12

__global__ void __launch_bounds__(384)
attn_kernel()
{
    __shared__ __align__(16) float lk_s[TXB * ACH * DKc];   // 1152
    __shared__ __align__(16) float lv_s[TXB * ACH * DKc];   // 1152
    __shared__ __align__(16) float sc_s[TXB * ACH * YB];    // 2304

    const int tid = threadIdx.x;
    const int yt = blockIdx.x % 3;
    const int xt = (blockIdx.x / 3) & 15;
    const int bh = blockIdx.x / 48;
    const int h  = bh % Hc;
    const int b  = bh / Hc;
    const int x0 = xt * TXB;
    const int yb = yt * YB;

    const int slab = NNc * DKc;  // 147456
    const float* lkbase = g_proj + (size_t)((0 * Bc + b) * Hc + h) * slab;
    const float* lvbase = g_proj + (size_t)((2 * Bc + b) * Hc + h) * slab;
    const float* rvbase = g_proj + (size_t)((3 * Bc + b) * Hc + h) * slab;
    const float* rkT    = g_rkT + (size_t)(b * Hc + h) * Nc * DKc * Nc;

    // phase-A identity: warp owns one a of the chunk, lanes = y
    const int wA = tid >> 5;          // 0..11
    const int lA = tid & 31;          // y-lane
    // phase-B identity: (g: tx-pair, yl, dq)
    const int g  = tid >> 7;          // 0..2 -> tx pair {2g, 2g+1}
    const int rr = tid & 127;
    const int yl = rr >> 2;           // 0..31
    const int dq = rr & 3;            // 0..3
    const int y  = yb + yl;

    float4 num0 = {0,0,0,0}, num1 = {0,0,0,0};
    float den0 = 0.f, den1 = 0.f;

    for (int a0 = 0; a0 < 96; a0 += ACH) {
        __syncthreads();   // previous phase B done with lk/lv/sc

        // ---- load lk/lv chunk: [tx][al][d], contiguous 192 floats per tx
        {
            // 288 float4 per array; 384 threads -> strided
            for (int i = tid; i < 2 * TXB * ACH * 4; i += 384) {
                int arr = i >= 288;
                int j   = arr ? i - 288 : i;       // 0..287
                int tx  = j / 48;
                int k   = j - tx * 48;             // float4 within tx-chunk
                const float* src = (arr ? lvbase : lkbase)
                                 + (size_t)((x0 + tx) * 96 + a0) * DKc;
                float* dst = (arr ? lv_s : lk_s) + tx * (ACH * DKc);
                ((float4*)dst)[k] = ((const float4*)src)[k];
            }
        }
        __syncthreads();   // lk/lv visible

        // ---- Phase A: scores for this chunk -> exp -> sc_s
        {
            const int a = a0 + wA;
            const float* rkp = rkT + ((size_t)a * DKc) * Nc + yb + lA;
            float r[16];
#pragma unroll
            for (int d = 0; d < 16; ++d) r[d] = rkp[(size_t)d * Nc];
#pragma unroll
            for (int tx = 0; tx < TXB; ++tx) {
                const float4* lp = (const float4*)(lk_s + (tx * ACH + wA) * DKc);
                float4 l0 = lp[0], l1 = lp[1], l2 = lp[2], l3 = lp[3];
                float s0 = l0.x * r[0]  + l0.y * r[1]  + l0.z * r[2]  + l0.w * r[3];
                float s1 = l1.x * r[4]  + l1.y * r[5]  + l1.z * r[6]  + l1.w * r[7];
                float s2 = l2.x * r[8]  + l2.y * r[9]  + l2.z * r[10] + l2.w * r[11];
                float s3 = l3.x * r[12] + l3.y * r[13] + l3.z * r[14] + l3.w * r[15];
                sc_s[(tx * ACH + wA) * YB + lA] = __expf((s0 + s1 + s2 + s3) * 0.25f);
            }
        }
        __syncthreads();   // sc visible

        // ---- Phase B: accumulate num/den for this chunk
        {
            const int tx0 = g * 2;
#pragma unroll
            for (int al = 0; al < ACH; ++al) {
                const int a = a0 + al;
                float4 rv = *(const float4*)(rvbase + ((size_t)(a * 96 + y)) * DKc + dq * 4);
                float e0 = sc_s[((tx0 + 0) * ACH + al) * YB + yl];
                float e1 = sc_s[((tx0 + 1) * ACH + al) * YB + yl];
                float4 v0 = *(const float4*)(lv_s + ((tx0 + 0) * ACH + al) * DKc + dq * 4);
                float4 v1 = *(const float4*)(lv_s + ((tx0 + 1) * ACH + al) * DKc + dq * 4);
                num0.x += e0 * (v0.x * rv.x);
                num0.y += e0 * (v0.y * rv.y);
                num0.z += e0 * (v0.z * rv.z);
                num0.w += e0 * (v0.w * rv.w);
                num1.x += e1 * (v1.x * rv.x);
                num1.y += e1 * (v1.y * rv.y);
                num1.z += e1 * (v1.z * rv.z);
                num1.w += e1 * (v1.w * rv.w);
                den0 += e0;
                den1 += e1;
            }
        }
    }

    // ---- normalize and store
    {
        float i0 = 1.f / den0;
        float i1 = 1.f / den1;
        float4 o0 = make_float4(num0.x * i0, num0.y * i0, num0.z * i0, num0.w * i0);
        float4 o1 = make_float4(num1.x * i1, num1.y * i1, num1.z * i1, num1.w * i1);
        size_t row0 = (size_t)b * NNc + (size_t)(x0 + g * 2 + 0) * 96 + y;
        size_t row1 = (size_t)b * NNc + (size_t)(x0 + g * 2 + 1) * 96 + y;
        *(float4*)&g_attout[row0 * 64 + h * 16 + dq * 4] = o0;
        *(float4*)&g_attout[row1 * 64 + h * 16 + dq * 4] = o1;
    }
}

// ---------------------------------------------------------------------------
// Kernel C: output projection (R4 proven shape).
// ---------------------------------------------------------------------------
__global__ void __launch_bounds__(256)
out_kernel(const float* __restrict__ w_out, const float* __restrict__ b_out,
           float* __restrict__ out)
{
    __shared__ __align__(16) float w_s[64 * A_WS_STRIDE];
    __shared__ __align__(16) float st_s[64 * 64];
    __shared__ float bias_s[64];

    const int tid = threadIdx.x;
    const int rowBase = blockIdx.x * 64;

    for (int idx = tid; idx < 4096; idx += 256) {
        int p = idx >> 6, k = idx & 63;
        w_s[k * A_WS_STRIDE + p] = w_out[idx];
    }
    if (tid < 64) bias_s[tid] = b_out[tid];
    {
        const float4* src = (const float4*)(g_attout + (size_t)rowBase * 64);
        float4* dst = (float4*)st_s;
        for (int i = tid; i < 1024; i += 256) dst[i] = src[i];
    }
    __syncthreads();

    const int p0 = (tid & 15) * 4;
    const int r0 = (tid >> 4) * 4;

    float acc[4][4];
#pragma unroll
    for (int i = 0; i < 4; ++i)
#pragma unroll
        for (int j = 0; j < 4; ++j) acc[i][j] = 0.f;

#pragma unroll 8
    for (int k = 0; k < 64; ++k) {
        float4 wv = *(const float4*)&w_s[k * A_WS_STRIDE + p0];
#pragma unroll
        for (int i = 0; i < 4; ++i) {
            float s = st_s[(r0 + i) * 64 + k];
            acc[i][0] += s * wv.x;
            acc[i][1] += s * wv.y;
            acc[i][2] += s * wv.z;
            acc[i][3] += s * wv.w;
        }
    }

    const float4 bv = *(const float4*)&bias_s[p0];
#pragma unroll
    for (int i = 0; i < 4; ++i) {
        int row = rowBase + r0 + i;
        float4 v;
        v.x = acc[i][0] + bv.x;
        v.y = acc[i][1] + bv.y;
        v.z = acc[i][2] + bv.z;
        v.w = acc[i][3] + bv.w;
        *(float4*)&out[(size_t)row * 64 + p0] = v;
    }
}

// ---------------------------------------------------------------------------
extern "C" void kernel_launch(void* const* d_in, const int* in_sizes, int n_in,
                              void* d_out, int out_size)
{
    const float* state = (const float*)d_in[0];
    const float* w_lk = (const float*)d_in[1];
    const float* b_lk = (const float*)d_in[2];
    const float* w_rk = (const float*)d_in[3];
    const float* b_rk = (const float*)d_in[4];
    const float* w_lv = (const float*)d_in[5];
    const float* b_lv = (const float*)d_in[6];
    const float* w_rv = (const float*)d_in[7];
    const float* b_rv = (const float*)d_in[8];
    const float* w_out = (const float*)d_in[9];
    const float* b_out = (const float*)d_in[10];
    float* out = (float*)d_out;

    dim3 gridA(ROWS_TOTAL / 64, 4);
    proj_kernel<<<gridA, 256>>>(
        state, w_lk, b_lk, w_rk, b_rk, w_lv, b_lv, w_rv, b_rv);

    // 8 (b,h) * 16 x-tiles * 3 y-tiles = 384 blocks
    attn_kernel<<<Bc * Hc * (Nc / TXB) * (Nc / YB), 384>>>();

    out_kernel<<<ROWS_TOTAL / 64, 256>>>(w_out, b_out, out);
}

// round 8
// speedup vs baseline: 1.2260x; 1.0004x over previous
#include <cuda_runtime.h>
#include <cuda_bf16.h>

// Problem constants
#define Bc 2
#define Nc 96
#define NNc 9216            // Nc*Nc
#define Dc 64
#define Hc 4
#define DKc 16
#define ROWS_TOTAL 18432    // Bc*NNc

// Scratch (device globals; allocation-free per harness rules)
// g_proj layout: [proj(4)][b(2)][h(4)][i(9216)][d(16)]  (rk slot unused)
__device__ float g_proj[4u * Bc * Hc * NNc * DKc];          // 18.9 MB
// rk transposed: [b][h][a(96)][d(16)][y(96)]
__device__ float g_rkT[(size_t)Bc * Hc * Nc * DKc * Nc];    // 4.7 MB
__device__ float g_attout[(size_t)ROWS_TOTAL * Dc];         // 4.7 MB

// ---------------------------------------------------------------------------
// Kernel A: projection (R3 proven shape).  proj==1 -> g_rkT transposed.
// ---------------------------------------------------------------------------
#define A_WS_STRIDE 68

__global__ void __launch_bounds__(256)
proj_kernel(const float* __restrict__ state,
            const float* __restrict__ w_lk, const float* __restrict__ b_lk,
            const float* __restrict__ w_rk, const float* __restrict__ b_rk,
            const float* __restrict__ w_lv, const float* __restrict__ b_lv,
            const float* __restrict__ w_rv, const float* __restrict__ b_rv)
{
    __shared__ __align__(16) float w_s[64 * A_WS_STRIDE];
    __shared__ __align__(16) float st_s[64 * 64];
    __shared__ float bias_s[64];

    const int tid = threadIdx.x;
    const int rowBase = blockIdx.x * 64;
    const int proj = blockIdx.y;

    const float* W = (proj == 0) ? w_lk : (proj == 1) ? w_rk
                    : (proj == 2) ? w_lv : w_rv;
    const float* Bv = (proj == 0) ? b_lk : (proj == 1) ? b_rk
                     : (proj == 2) ? b_lv : b_rv;

    for (int idx = tid; idx < 4096; idx += 256) {
        int p = idx >> 6, k = idx & 63;
        w_s[k * A_WS_STRIDE + p] = W[idx];
    }
    if (tid < 64) bias_s[tid] = Bv[tid];
    {
        const float4* src = (const float4*)(state + (size_t)rowBase * 64);
        float4* dst = (float4*)st_s;
        for (int i = tid; i < 1024; i += 256) dst[i] = src[i];
    }
    __syncthreads();

    const int p0 = (tid & 15) * 4;
    const int r0 = (tid >> 4) * 4;

    float acc[4][4];
#pragma unroll
    for (int i = 0; i < 4; ++i)
#pragma unroll
        for (int j = 0; j < 4; ++j) acc[i][j] = 0.f;

#pragma unroll 8
    for (int k = 0; k < 64; ++k) {
        float4 wv = *(const float4*)&w_s[k * A_WS_STRIDE + p0];
#pragma unroll
        for (int i = 0; i < 4; ++i) {
            float s = st_s[(r0 + i) * 64 + k];
            acc[i][0] += s * wv.x;
            acc[i][1] += s * wv.y;
            acc[i][2] += s * wv.z;
            acc[i][3] += s * wv.w;
        }
    }

    const float4 bv = *(const float4*)&bias_s[p0];
    const int h  = p0 >> 4;
    const int d0 = p0 & 15;

#pragma unroll
    for (int i = 0; i < 4; ++i) {
        int row = rowBase + r0 + i;
        int b   = row / NNc;
        int idx = row - b * NNc;
        float v0 = acc[i][0] + bv.x;
        float v1 = acc[i][1] + bv.y;
        float v2 = acc[i][2] + bv.z;
        float v3 = acc[i][3] + bv.w;
        if (proj == 1) {
            int a = idx / 96, y = idx - a * 96;
            size_t base = ((((size_t)(b * Hc + h) * Nc + a) * DKc + d0) * Nc) + y;
            g_rkT[base]       = v0;
            g_rkT[base + 96]  = v1;
            g_rkT[base + 192] = v2;
            g_rkT[base + 288] = v3;
        } else {
            size_t off = ((size_t)((proj * Bc + b) * Hc + h) * NNc + idx) * DKc + d0;
            float4 v; v.x = v0; v.y = v1; v.z = v2; v.w = v3;
            *(float4*)&g_proj[off] = v;
        }
    }
}

// ---------------------------------------------------------------------------
// Kernel B: streaming edge-attention, no-max softmax.
// Block = (b, h, x-tile of 6, y-tile of 32).  a in chunks of 12.
// Phase B splits the a-range 3 ways (not tx) -> each rv element loaded ONCE
// per block; each thread accumulates all 6 tx.  3-step smem reduction merges
// the a-splits at block end (overlaid on lk/lv/sc).
// ---------------------------------------------------------------------------
#define TXB 6
#define YB  32
#define ACH 12

__global__ void __launch_bounds__(384, 3)
attn_kernel()
{
    __shared__ __align__(16) float lk_s[TXB * ACH * DKc];   // 1152
    __shared__ __align__(16) float lv_s[TXB * ACH * DKc];   // 1152
    __shared__ __align__(16) float sc_s[TXB * ACH * YB];    // 2304
    // overlay for final reduction (reuses lk/lv/sc space: 4608 >= 3264)
    float* part  = lk_s;                         // 6*32*16 = 3072 floats
    float* pden  = sc_s + 1000;                  // 6*32 = 192 floats (inside sc_s)

    const int tid = threadIdx.x;
    const int yt = blockIdx.x % 3;
    const int xt = (blockIdx.x / 3) & 15;
    const int bh = blockIdx.x / 48;
    const int h  = bh % Hc;
    const int b  = bh / Hc;
    const int x0 = xt * TXB;
    const int yb = yt * YB;

    const int slab = NNc * DKc;  // 147456
    const float* lkbase = g_proj + (size_t)((0 * Bc + b) * Hc + h) * slab;
    const float* lvbase = g_proj + (size_t)((2 * Bc + b) * Hc + h) * slab;
    const float* rvbase = g_proj + (size_t)((3 * Bc + b) * Hc + h) * slab;
    const float* rkT    = g_rkT + (size_t)(b * Hc + h) * Nc * DKc * Nc;

    // phase-A identity: warp owns one a of the chunk, lanes = y
    const int wA = tid >> 5;          // 0..11
    const int lA = tid & 31;          // y-lane
    // phase-B identity: (as: a-slice, yl, dq)
    const int as = tid >> 7;          // 0..2 -> a-slice of 4 within chunk
    const int rr = tid & 127;
    const int yl = rr >> 2;           // 0..31
    const int dq = rr & 3;            // 0..3
    const int y  = yb + yl;

    float4 num[TXB];
    float  den[TXB];
#pragma unroll
    for (int t = 0; t < TXB; ++t) { num[t] = make_float4(0,0,0,0); den[t] = 0.f; }

    for (int a0 = 0; a0 < 96; a0 += ACH) {
        __syncthreads();   // previous phase B done with lk/lv/sc

        // ---- load lk/lv chunk: [tx][al][d], contiguous 192 floats per tx
        for (int i = tid; i < 2 * TXB * ACH * 4; i += 384) {
            int arr = i >= 288;
            int j   = arr ? i - 288 : i;       // 0..287
            int tx  = j / 48;
            int k   = j - tx * 48;             // float4 within tx-chunk
            const float* src = (arr ? lvbase : lkbase)
                             + (size_t)((x0 + tx) * 96 + a0) * DKc;
            float* dst = (arr ? lv_s : lk_s) + tx * (ACH * DKc);
            ((float4*)dst)[k] = ((const float4*)src)[k];
        }
        __syncthreads();   // lk/lv visible

        // ---- Phase A: scores for this chunk -> exp -> sc_s (d in 2 halves)
        {
            const int a = a0 + wA;
            const float* rkp = rkT + ((size_t)a * DKc) * Nc + yb + lA;
            float ps[TXB];
            {
                float r[8];
#pragma unroll
                for (int d = 0; d < 8; ++d) r[d] = rkp[(size_t)d * Nc];
#pragma unroll
                for (int tx = 0; tx < TXB; ++tx) {
                    const float4* lp = (const float4*)(lk_s + (tx * ACH + wA) * DKc);
                    float4 l0 = lp[0], l1 = lp[1];
                    ps[tx] = l0.x * r[0] + l0.y * r[1] + l0.z * r[2] + l0.w * r[3]
                           + l1.x * r[4] + l1.y * r[5] + l1.z * r[6] + l1.w * r[7];
                }
            }
            {
                float r[8];
#pragma unroll
                for (int d = 0; d < 8; ++d) r[d] = rkp[(size_t)(8 + d) * Nc];
#pragma unroll
                for (int tx = 0; tx < TXB; ++tx) {
                    const float4* lp = (const float4*)(lk_s + (tx * ACH + wA) * DKc + 8);
                    float4 l2 = lp[0], l3 = lp[1];
                    float s = ps[tx]
                            + l2.x * r[0] + l2.y * r[1] + l2.z * r[2] + l2.w * r[3]
                            + l3.x * r[4] + l3.y * r[5] + l3.z * r[6] + l3.w * r[7];
                    sc_s[(tx * ACH + wA) * YB + lA] = __expf(s * 0.25f);
                }
            }
        }
        __syncthreads();   // sc visible

        // ---- Phase B: a-slice of 4, all 6 tx; rv loaded once per (a,y,d)
#pragma unroll
        for (int j = 0; j < 4; ++j) {
            const int al = as * 4 + j;
            const int a  = a0 + al;
            float4 rv = *(const float4*)(rvbase + ((size_t)(a * 96 + y)) * DKc + dq * 4);
#pragma unroll
            for (int tx = 0; tx < TXB; ++tx) {
                float e = sc_s[(tx * ACH + al) * YB + yl];
                float4 v = *(const float4*)(lv_s + (tx * ACH + al) * DKc + dq * 4);
                num[tx].x += e * (v.x * rv.x);
                num[tx].y += e * (v.y * rv.y);
                num[tx].z += e * (v.z * rv.z);
                num[tx].w += e * (v.w * rv.w);
                den[tx]   += e;
            }
        }
    }

    // ---- merge the 3 a-slices via smem (overlay), then normalize and store
    __syncthreads();   // all phase B reads of sc/lv done; overlay is safe
#pragma unroll
    for (int step = 0; step < 3; ++step) {
        if (as == step) {
            float4* p4 = (float4*)part;
            if (step == 0) {
#pragma unroll
                for (int tx = 0; tx < TXB; ++tx) {
                    p4[(tx * YB + yl) * 4 + dq] = num[tx];
                    if (dq == 0) pden[tx * YB + yl] = den[tx];
                }
            } else {
#pragma unroll
                for (int tx = 0; tx < TXB; ++tx) {
                    float4 c = p4[(tx * YB + yl) * 4 + dq];
                    c.x += num[tx].x; c.y += num[tx].y;
                    c.z += num[tx].z; c.w += num[tx].w;
                    p4[(tx * YB + yl) * 4 + dq] = c;
                    if (dq == 0) pden[tx * YB + yl] += den[tx];
                }
            }
        }
        __syncthreads();
    }

    // 768 float4 outputs, 384 threads -> 2 each
    {
        const float4* p4 = (const float4*)part;
#pragma unroll
        for (int r = 0; r < 2; ++r) {
            int idx = tid + r * 384;            // (tx*YB + yl)*4 + dq
            int dqo = idx & 3;
            int cyl = (idx >> 2) & 31;
            int tx  = idx >> 7;
            float inv = 1.f / pden[tx * YB + cyl];
            float4 o = p4[idx];
            o.x *= inv; o.y *= inv; o.z *= inv; o.w *= inv;
            size_t row = (size_t)b * NNc + (size_t)(x0 + tx) * 96 + (yb + cyl);
            *(float4*)&g_attout[row * 64 + h * 16 + dqo * 4] = o;
        }
    }
}

// ---------------------------------------------------------------------------
// Kernel C: output projection (R4 proven shape).
// ---------------------------------------------------------------------------
__global__ void __launch_bounds__(256)
out_kernel(const float* __restrict__ w_out, const float* __restrict__ b_out,
           float* __restrict__ out)
{
    __shared__ __align__(16) float w_s[64 * A_WS_STRIDE];
    __shared__ __align__(16) float st_s[64 * 64];
    __shared__ float bias_s[64];

    const int tid = threadIdx.x;
    const int rowBase = blockIdx.x * 64;

    for (int idx = tid; idx < 4096; idx += 256) {
        int p = idx >> 6, k = idx & 63;
        w_s[k * A_WS_STRIDE + p] = w_out[idx];
    }
    if (tid < 64) bias_s[tid] = b_out[tid];
    {
        const float4* src = (const float4*)(g_attout + (size_t)rowBase * 64);
        float4* dst = (float4*)st_s;
        for (int i = tid; i < 1024; i += 256) dst[i] = src[i];
    }
    __syncthreads();

    const int p0 = (tid & 15) * 4;
    const int r0 = (tid >> 4) * 4;

    float acc[4][4];
#pragma unroll
    for (int i = 0; i < 4; ++i)
#pragma unroll
        for (int j = 0; j < 4; ++j) acc[i][j] = 0.f;

#pragma unroll 8
    for (int k = 0; k < 64; ++k) {
        float4 wv = *(const float4*)&w_s[k * A_WS_STRIDE + p0];
#pragma unroll
        for (int i = 0; i < 4; ++i) {
            float s = st_s[(r0 + i) * 64 + k];
            acc[i][0] += s * wv.x;
            acc[i][1] += s * wv.y;
            acc[i][2] += s * wv.z;
            acc[i][3] += s * wv.w;
        }
    }

    const float4 bv = *(const float4*)&bias_s[p0];
#pragma unroll
    for (int i = 0; i < 4; ++i) {
        int row = rowBase + r0 + i;
        float4 v;
        v.x = acc[i][0] + bv.x;
        v.y = acc[i][1] + bv.y;
        v.z = acc[i][2] + bv.z;
        v.w = acc[i][3] + bv.w;
        *(float4*)&out[(size_t)row * 64 + p0] = v;
    }
}

// ---------------------------------------------------------------------------
extern "C" void kernel_launch(void* const* d_in, const int* in_sizes, int n_in,
                              void* d_out, int out_size)
{
    const float* state = (const float*)d_in[0];
    const float* w_lk = (const float*)d_in[1];
    const float* b_lk = (const float*)d_in[2];
    const float* w_rk = (const float*)d_in[3];
    const float* b_rk = (const float*)d_in[4];
    const float* w_lv = (const float*)d_in[5];
    const float* b_lv = (const float*)d_in[6];
    const float* w_rv = (const float*)d_in[7];
    const float* b_rv = (const float*)d_in[8];
    const float* w_out = (const float*)d_in[9];
    const float* b_out = (const float*)d_in[10];
    float* out = (float*)d_out;

    dim3 gridA(ROWS_TOTAL / 64, 4);
    proj_kernel<<<gridA, 256>>>(
        state, w_lk, b_lk, w_rk, b_rk, w_lv, b_lv, w_rv, b_rv);

    // 8 (b,h) * 16 x-tiles * 3 y-tiles = 384 blocks
    attn_kernel<<<Bc * Hc * (Nc / TXB) * (Nc / YB), 384>>>();

    out_kernel<<<ROWS_TOTAL / 64, 256>>>(w_out, b_out, out);
}

// round 9
// speedup vs baseline: 1.2678x; 1.0341x over previous
#include <cuda_runtime.h>
#include <cuda_bf16.h>

// Problem constants
#define Bc 2
#define Nc 96
#define NNc 9216            // Nc*Nc
#define Dc 64
#define Hc 4
#define DKc 16
#define ROWS_TOTAL 18432    // Bc*NNc

// Scratch (device globals; allocation-free per harness rules)
// g_proj layout: [proj(4)][b(2)][h(4)][i(9216)][d(16)]
__device__ float g_proj[4u * Bc * Hc * NNc * DKc];          // 18.9 MB
// rk transposed: [b][h][a(96)][d(16)][y(96)]
__device__ float g_rkT[(size_t)Bc * Hc * Nc * DKc * Nc];    // 4.7 MB
__device__ float g_attout[(size_t)ROWS_TOTAL * Dc];         // 4.7 MB

// ---------------------------------------------------------------------------
// Kernel A: projection (R3 proven shape), now branch-free: ALL projections
// write the standard coalesced [i][d] layout (rk transpose moved to kernel T).
// ---------------------------------------------------------------------------
#define A_WS_STRIDE 68

__global__ void __launch_bounds__(256)
proj_kernel(const float* __restrict__ state,
            const float* __restrict__ w_lk, const float* __restrict__ b_lk,
            const float* __restrict__ w_rk, const float* __restrict__ b_rk,
            const float* __restrict__ w_lv, const float* __restrict__ b_lv,
            const float* __restrict__ w_rv, const float* __restrict__ b_rv)
{
    __shared__ __align__(16) float w_s[64 * A_WS_STRIDE];
    __shared__ __align__(16) float st_s[64 * 64];
    __shared__ float bias_s[64];

    const int tid = threadIdx.x;
    const int rowBase = blockIdx.x * 64;
    const int proj = blockIdx.y;

    const float* W = (proj == 0) ? w_lk : (proj == 1) ? w_rk
                    : (proj == 2) ? w_lv : w_rv;
    const float* Bv = (proj == 0) ? b_lk : (proj == 1) ? b_rk
                     : (proj == 2) ? b_lv : b_rv;

    for (int idx = tid; idx < 4096; idx += 256) {
        int p = idx >> 6, k = idx & 63;
        w_s[k * A_WS_STRIDE + p] = W[idx];
    }
    if (tid < 64) bias_s[tid] = Bv[tid];
    {
        const float4* src = (const float4*)(state + (size_t)rowBase * 64);
        float4* dst = (float4*)st_s;
        for (int i = tid; i < 1024; i += 256) dst[i] = src[i];
    }
    __syncthreads();

    const int p0 = (tid & 15) * 4;
    const int r0 = (tid >> 4) * 4;

    float acc[4][4];
#pragma unroll
    for (int i = 0; i < 4; ++i)
#pragma unroll
        for (int j = 0; j < 4; ++j) acc[i][j] = 0.f;

#pragma unroll 8
    for (int k = 0; k < 64; ++k) {
        float4 wv = *(const float4*)&w_s[k * A_WS_STRIDE + p0];
#pragma unroll
        for (int i = 0; i < 4; ++i) {
            float s = st_s[(r0 + i) * 64 + k];
            acc[i][0] += s * wv.x;
            acc[i][1] += s * wv.y;
            acc[i][2] += s * wv.z;
            acc[i][3] += s * wv.w;
        }
    }

    const float4 bv = *(const float4*)&bias_s[p0];
    const int h  = p0 >> 4;
    const int d0 = p0 & 15;

#pragma unroll
    for (int i = 0; i < 4; ++i) {
        int row = rowBase + r0 + i;
        int b   = row / NNc;
        int idx = row - b * NNc;
        float4 v;
        v.x = acc[i][0] + bv.x;
        v.y = acc[i][1] + bv.y;
        v.z = acc[i][2] + bv.z;
        v.w = acc[i][3] + bv.w;
        size_t off = ((size_t)((proj * Bc + b) * Hc + h) * NNc + idx) * DKc + d0;
        *(float4*)&g_proj[off] = v;
    }
}

// ---------------------------------------------------------------------------
// Kernel T: transpose rk [b][h][a·96+y][d] -> rkT [b][h][a][d][y].
// One block per (b,h,a); coalesced LDG.128 in, coalesced STG.128 out.
// ---------------------------------------------------------------------------
__global__ void __launch_bounds__(128)
rkT_kernel()
{
    __shared__ float t[96][17];

    const int tid = threadIdx.x;
    const int a  = blockIdx.x % Nc;
    const int bh = blockIdx.x / Nc;

    const float* src = g_proj + (size_t)(1 * Bc * Hc + bh) * NNc * DKc
                     + (size_t)(a * 96) * DKc;
    float* dst = g_rkT + ((size_t)bh * Nc + a) * DKc * Nc;

    // load 96 y x 16 d = 384 float4, coalesced
    const float4* s4 = (const float4*)src;
#pragma unroll
    for (int r = 0; r < 3; ++r) {
        int i = tid + r * 128;          // i = y*4 + dq
        float4 v = s4[i];
        int y = i >> 2, dq = (i & 3) * 4;
        t[y][dq + 0] = v.x;
        t[y][dq + 1] = v.y;
        t[y][dq + 2] = v.z;
        t[y][dq + 3] = v.w;
    }
    __syncthreads();

    // write 16 d rows x 96 y = 384 float4, coalesced
    float4* d4 = (float4*)dst;
#pragma unroll
    for (int r = 0; r < 3; ++r) {
        int i = tid + r * 128;          // i = d*24 + yq
        int d  = i / 24;
        int y0 = (i - d * 24) * 4;
        float4 v;
        v.x = t[y0 + 0][d];
        v.y = t[y0 + 1][d];
        v.z = t[y0 + 2][d];
        v.w = t[y0 + 3][d];
        d4[i] = v;
    }
}

// ---------------------------------------------------------------------------
// Kernel B: streaming edge-attention, no-max softmax (R7/R8 structure).
// Block = (b, h, x-tile of 6, y-tile of 32).  a in chunks of 24 (4 rounds,
// half the barriers of R8).  Phase B splits a-range 3 ways; rv loaded once.
// smem = 36.9 KB.
// ---------------------------------------------------------------------------
#define TXB 6
#define YB  32
#define ACH 24
#define CF4 (TXB * ACH * DKc / 4)   // 576 float4 per lk/lv chunk

__global__ void __launch_bounds__(384, 3)
attn_kernel()
{
    __shared__ __align__(16) float lk_s[TXB * ACH * DKc];   // 2304
    __shared__ __align__(16) float lv_s[TXB * ACH * DKc];   // 2304
    __shared__ __align__(16) float sc_s[TXB * ACH * YB];    // 4608
    // overlay for final reduction: part needs 3072 floats (lk_s+lv_s = 4608)
    float* part = lk_s;
    float* pden = sc_s + 1024;       // 192 floats inside sc_s

    const int tid = threadIdx.x;
    const int yt = blockIdx.x % 3;
    const int xt = (blockIdx.x / 3) & 15;
    const int bh = blockIdx.x / 48;
    const int h  = bh % Hc;
    const int b  = bh / Hc;
    const int x0 = xt * TXB;
    const int yb = yt * YB;

    const int slab = NNc * DKc;  // 147456
    const float* lkbase = g_proj + (size_t)((0 * Bc + b) * Hc + h) * slab;
    const float* lvbase = g_proj + (size_t)((2 * Bc + b) * Hc + h) * slab;
    const float* rvbase = g_proj + (size_t)((3 * Bc + b) * Hc + h) * slab;
    const float* rkT    = g_rkT + (size_t)(b * Hc + h) * Nc * DKc * Nc;

    // phase-A identity: warp handles 2 a's of the 24-chunk, lanes = y
    const int wA = tid >> 5;          // 0..11
    const int lA = tid & 31;          // y-lane
    // phase-B identity: (as: a-slice of 8, yl, dq)
    const int as = tid >> 7;          // 0..2
    const int rr = tid & 127;
    const int yl = rr >> 2;           // 0..31
    const int dq = rr & 3;            // 0..3
    const int y  = yb + yl;

    float4 num[TXB];
    float  den[TXB];
#pragma unroll
    for (int t = 0; t < TXB; ++t) { num[t] = make_float4(0,0,0,0); den[t] = 0.f; }

    for (int a0 = 0; a0 < 96; a0 += ACH) {
        __syncthreads();   // previous phase B done with lk/lv/sc

        // ---- load lk/lv chunk: [tx][al][d], 576 float4 each
        for (int i = tid; i < 2 * CF4; i += 384) {
            int arr = i >= CF4;
            int j   = arr ? i - CF4 : i;       // 0..575
            int tx  = j / (ACH * DKc / 4);     // /96
            int k   = j - tx * (ACH * DKc / 4);
            const float* src = (arr ? lvbase : lkbase)
                             + (size_t)((x0 + tx) * 96 + a0) * DKc;
            float* dst = (arr ? lv_s : lk_s) + tx * (ACH * DKc);
            ((float4*)dst)[k] = ((const float4*)src)[k];
        }
        __syncthreads();   // lk/lv visible

        // ---- Phase A: scores -> exp -> sc_s; each warp does 2 a's
#pragma unroll
        for (int rep = 0; rep < 2; ++rep) {
            const int al = wA + rep * 12;
            const int a  = a0 + al;
            const float* rkp = rkT + ((size_t)a * DKc) * Nc + yb + lA;
            float ps[TXB];
            {
                float r[8];
#pragma unroll
                for (int d = 0; d < 8; ++d) r[d] = rkp[(size_t)d * Nc];
#pragma unroll
                for (int tx = 0; tx < TXB; ++tx) {
                    const float4* lp = (const float4*)(lk_s + (tx * ACH + al) * DKc);
                    float4 l0 = lp[0], l1 = lp[1];
                    ps[tx] = l0.x * r[0] + l0.y * r[1] + l0.z * r[2] + l0.w * r[3]
                           + l1.x * r[4] + l1.y * r[5] + l1.z * r[6] + l1.w * r[7];
                }
            }
            {
                float r[8];
#pragma unroll
                for (int d = 0; d < 8; ++d) r[d] = rkp[(size_t)(8 + d) * Nc];
#pragma unroll
                for (int tx = 0; tx < TXB; ++tx) {
                    const float4* lp = (const float4*)(lk_s + (tx * ACH + al) * DKc + 8);
                    float4 l2 = lp[0], l3 = lp[1];
                    float s = ps[tx]
                            + l2.x * r[0] + l2.y * r[1] + l2.z * r[2] + l2.w * r[3]
                            + l3.x * r[4] + l3.y * r[5] + l3.z * r[6] + l3.w * r[7];
                    sc_s[(tx * ACH + al) * YB + lA] = __expf(s * 0.25f);
                }
            }
        }
        __syncthreads();   // sc visible

        // ---- Phase B: a-slice of 8, all 6 tx; rv loaded once per (a,y,d)
#pragma unroll
        for (int j = 0; j < 8; ++j) {
            const int al = as * 8 + j;
            const int a  = a0 + al;
            float4 rv = *(const float4*)(rvbase + ((size_t)(a * 96 + y)) * DKc + dq * 4);
#pragma unroll
            for (int tx = 0; tx < TXB; ++tx) {
                float e = sc_s[(tx * ACH + al) * YB + yl];
                float4 v = *(const float4*)(lv_s + (tx * ACH + al) * DKc + dq * 4);
                num[tx].x += e * (v.x * rv.x);
                num[tx].y += e * (v.y * rv.y);
                num[tx].z += e * (v.z * rv.z);
                num[tx].w += e * (v.w * rv.w);
                den[tx]   += e;
            }
        }
    }

    // ---- merge the 3 a-slices via smem (overlay), then normalize and store
    __syncthreads();
#pragma unroll
    for (int step = 0; step < 3; ++step) {
        if (as == step) {
            float4* p4 = (float4*)part;
            if (step == 0) {
#pragma unroll
                for (int tx = 0; tx < TXB; ++tx) {
                    p4[(tx * YB + yl) * 4 + dq] = num[tx];
                    if (dq == 0) pden[tx * YB + yl] = den[tx];
                }
            } else {
#pragma unroll
                for (int tx = 0; tx < TXB; ++tx) {
                    float4 c = p4[(tx * YB + yl) * 4 + dq];
                    c.x += num[tx].x; c.y += num[tx].y;
                    c.z += num[tx].z; c.w += num[tx].w;
                    p4[(tx * YB + yl) * 4 + dq] = c;
                    if (dq == 0) pden[tx * YB + yl] += den[tx];
                }
            }
        }
        __syncthreads();
    }

    // 768 float4 outputs, 384 threads -> 2 each
    {
        const float4* p4 = (const float4*)part;
#pragma unroll
        for (int r = 0; r < 2; ++r) {
            int idx = tid + r * 384;            // (tx*YB + yl)*4 + dq
            int dqo = idx & 3;
            int cyl = (idx >> 2) & 31;
            int tx  = idx >> 7;
            float inv = 1.f / pden[tx * YB + cyl];
            float4 o = p4[idx];
            o.x *= inv; o.y *= inv; o.z *= inv; o.w *= inv;
            size_t row = (size_t)b * NNc + (size_t)(x0 + tx) * 96 + (yb + cyl);
            *(float4*)&g_attout[row * 64 + h * 16 + dqo * 4] = o;
        }
    }
}

// ---------------------------------------------------------------------------
// Kernel C: output projection (R4 proven shape).
// ---------------------------------------------------------------------------
__global__ void __launch_bounds__(256)
out_kernel(const float* __restrict__ w_out, const float* __restrict__ b_out,
           float* __restrict__ out)
{
    __shared__ __align__(16) float w_s[64 * A_WS_STRIDE];
    __shared__ __align__(16) float st_s[64 * 64];
    __shared__ float bias_s[64];

    const int tid = threadIdx.x;
    const int rowBase = blockIdx.x * 64;

    for (int idx = tid; idx < 4096; idx += 256) {
        int p = idx >> 6, k = idx & 63;
        w_s[k * A_WS_STRIDE + p] = w_out[idx];
    }
    if (tid < 64) bias_s[tid] = b_out[tid];
    {
        const float4* src = (const float4*)(g_attout + (size_t)rowBase * 64);
        float4* dst = (float4*)st_s;
        for (int i = tid; i < 1024; i += 256) dst[i] = src[i];
    }
    __syncthreads();

    const int p0 = (tid & 15) * 4;
    const int r0 = (tid >> 4) * 4;

    float acc[4][4];
#pragma unroll
    for (int i = 0; i < 4; ++i)
#pragma unroll
        for (int j = 0; j < 4; ++j) acc[i][j] = 0.f;

#pragma unroll 8
    for (int k = 0; k < 64; ++k) {
        float4 wv = *(const float4*)&w_s[k * A_WS_STRIDE + p0];
#pragma unroll
        for (int i = 0; i < 4; ++i) {
            float s = st_s[(r0 + i) * 64 + k];
            acc[i][0] += s * wv.x;
            acc[i][1] += s * wv.y;
            acc[i][2] += s * wv.z;
            acc[i][3] += s * wv.w;
        }
    }

    const float4 bv = *(const float4*)&bias_s[p0];
#pragma unroll
    for (int i = 0; i < 4; ++i) {
        int row = rowBase + r0 + i;
        float4 v;
        v.x = acc[i][0] + bv.x;
        v.y = acc[i][1] + bv.y;
        v.z = acc[i][2] + bv.z;
        v.w = acc[i][3] + bv.w;
        *(float4*)&out[(size_t)row * 64 + p0] = v;
    }
}

// ---------------------------------------------------------------------------
extern "C" void kernel_launch(void* const* d_in, const int* in_sizes, int n_in,
                              void* d_out, int out_size)
{
    const float* state = (const float*)d_in[0];
    const float* w_lk = (const float*)d_in[1];
    const float* b_lk = (const float*)d_in[2];
    const float* w_rk = (const float*)d_in[3];
    const float* b_rk = (const float*)d_in[4];
    const float* w_lv = (const float*)d_in[5];
    const float* b_lv = (const float*)d_in[6];
    const float* w_rv = (const float*)d_in[7];
    const float* b_rv = (const float*)d_in[8];
    const float* w_out = (const float*)d_in[9];
    const float* b_out = (const float*)d_in[10];
    float* out = (float*)d_out;

    dim3 gridA(ROWS_TOTAL / 64, 4);
    proj_kernel<<<gridA, 256>>>(
        state, w_lk, b_lk, w_rk, b_rk, w_lv, b_lv, w_rv, b_rv);

    rkT_kernel<<<Bc * Hc * Nc, 128>>>();

    // 8 (b,h) * 16 x-tiles * 3 y-tiles = 384 blocks
    attn_kernel<<<Bc * Hc * (Nc / TXB) * (Nc / YB), 384>>>();

    out_kernel<<<ROWS_TOTAL / 64, 256>>>(w_out, b_out, out);
}

// round 10
// speedup vs baseline: 1.3003x; 1.0257x over previous
#include <cuda_runtime.h>
#include <cuda_bf16.h>

// Problem constants
#define Bc 2
#define Nc 96
#define NNc 9216            // Nc*Nc
#define Dc 64
#define Hc 4
#define DKc 16
#define ROWS_TOTAL 18432    // Bc*NNc

// Scratch (device globals; allocation-free per harness rules)
// g_proj layout: [proj(4)][b(2)][h(4)][i(9216)][d(16)]
__device__ float g_proj[4u * Bc * Hc * NNc * DKc];          // 18.9 MB
// rk transposed: [b][h][a(96)][d(16)][y(96)]
__device__ float g_rkT[(size_t)Bc * Hc * Nc * DKc * Nc];    // 4.7 MB
__device__ float g_attout[(size_t)ROWS_TOTAL * Dc];         // 4.7 MB

// ---------------------------------------------------------------------------
// Kernel A: projection.  32 rows x 64 cols per block, 128 threads, 4x4 tile.
// Small blocks -> grid 2304 -> fine wave granularity + high occupancy.
// ---------------------------------------------------------------------------
#define A_WS_STRIDE 68

__global__ void __launch_bounds__(128)
proj_kernel(const float* __restrict__ state,
            const float* __restrict__ w_lk, const float* __restrict__ b_lk,
            const float* __restrict__ w_rk, const float* __restrict__ b_rk,
            const float* __restrict__ w_lv, const float* __restrict__ b_lv,
            const float* __restrict__ w_rv, const float* __restrict__ b_rv)
{
    __shared__ __align__(16) float w_s[64 * A_WS_STRIDE];
    __shared__ __align__(16) float st_s[32 * 64];
    __shared__ float bias_s[64];

    const int tid = threadIdx.x;
    const int rowBase = blockIdx.x * 32;
    const int proj = blockIdx.y;

    const float* W = (proj == 0) ? w_lk : (proj == 1) ? w_rk
                    : (proj == 2) ? w_lv : w_rv;
    const float* Bv = (proj == 0) ? b_lk : (proj == 1) ? b_rk
                     : (proj == 2) ? b_lv : b_rv;

    // Weights transposed: w_s[k][p] = W[p][k]
    for (int idx = tid; idx < 4096; idx += 128) {
        int p = idx >> 6, k = idx & 63;
        w_s[k * A_WS_STRIDE + p] = W[idx];
    }
    if (tid < 64) bias_s[tid] = Bv[tid];
    {
        const float4* src = (const float4*)(state + (size_t)rowBase * 64);
        float4* dst = (float4*)st_s;
#pragma unroll
        for (int i = 0; i < 4; ++i) dst[tid + i * 128] = src[tid + i * 128];
    }
    __syncthreads();

    const int p0 = (tid & 15) * 4;   // 16 col groups
    const int r0 = (tid >> 4) * 4;   // 8 row groups

    float acc[4][4];
#pragma unroll
    for (int i = 0; i < 4; ++i)
#pragma unroll
        for (int j = 0; j < 4; ++j) acc[i][j] = 0.f;

#pragma unroll 8
    for (int k = 0; k < 64; ++k) {
        float4 wv = *(const float4*)&w_s[k * A_WS_STRIDE + p0];
#pragma unroll
        for (int i = 0; i < 4; ++i) {
            float s = st_s[(r0 + i) * 64 + k];
            acc[i][0] += s * wv.x;
            acc[i][1] += s * wv.y;
            acc[i][2] += s * wv.z;
            acc[i][3] += s * wv.w;
        }
    }

    const float4 bv = *(const float4*)&bias_s[p0];
    const int h  = p0 >> 4;
    const int d0 = p0 & 15;

#pragma unroll
    for (int i = 0; i < 4; ++i) {
        int row = rowBase + r0 + i;
        int b   = row / NNc;
        int idx = row - b * NNc;
        float4 v;
        v.x = acc[i][0] + bv.x;
        v.y = acc[i][1] + bv.y;
        v.z = acc[i][2] + bv.z;
        v.w = acc[i][3] + bv.w;
        size_t off = ((size_t)((proj * Bc + b) * Hc + h) * NNc + idx) * DKc + d0;
        *(float4*)&g_proj[off] = v;
    }
}

// ---------------------------------------------------------------------------
// Kernel T: transpose rk [b][h][a·96+y][d] -> rkT [b][h][a][d][y].
// ---------------------------------------------------------------------------
__global__ void __launch_bounds__(128)
rkT_kernel()
{
    __shared__ float t[96][17];

    const int tid = threadIdx.x;
    const int a  = blockIdx.x % Nc;
    const int bh = blockIdx.x / Nc;

    const float* src = g_proj + (size_t)(1 * Bc * Hc + bh) * NNc * DKc
                     + (size_t)(a * 96) * DKc;
    float* dst = g_rkT + ((size_t)bh * Nc + a) * DKc * Nc;

    const float4* s4 = (const float4*)src;
#pragma unroll
    for (int r = 0; r < 3; ++r) {
        int i = tid + r * 128;          // i = y*4 + dq
        float4 v = s4[i];
        int y = i >> 2, dq = (i & 3) * 4;
        t[y][dq + 0] = v.x;
        t[y][dq + 1] = v.y;
        t[y][dq + 2] = v.z;
        t[y][dq + 3] = v.w;
    }
    __syncthreads();

    float4* d4 = (float4*)dst;
#pragma unroll
    for (int r = 0; r < 3; ++r) {
        int i = tid + r * 128;          // i = d*24 + yq
        int d  = i / 24;
        int y0 = (i - d * 24) * 4;
        float4 v;
        v.x = t[y0 + 0][d];
        v.y = t[y0 + 1][d];
        v.z = t[y0 + 2][d];
        v.w = t[y0 + 3][d];
        d4[i] = v;
    }
}

// ---------------------------------------------------------------------------
// Kernel B: streaming edge-attention, no-max softmax (R9 proven, unchanged).
// ---------------------------------------------------------------------------
#define TXB 6
#define YB  32
#define ACH 24
#define CF4 (TXB * ACH * DKc / 4)   // 576 float4 per lk/lv chunk

__global__ void __launch_bounds__(384, 3)
attn_kernel()
{
    __shared__ __align__(16) float lk_s[TXB * ACH * DKc];   // 2304
    __shared__ __align__(16) float lv_s[TXB * ACH * DKc];   // 2304
    __shared__ __align__(16) float sc_s[TXB * ACH * YB];    // 4608
    float* part = lk_s;
    float* pden = sc_s + 1024;

    const int tid = threadIdx.x;
    const int yt = blockIdx.x % 3;
    const int xt = (blockIdx.x / 3) & 15;
    const int bh = blockIdx.x / 48;
    const int h  = bh % Hc;
    const int b  = bh / Hc;
    const int x0 = xt * TXB;
    const int yb = yt * YB;

    const int slab = NNc * DKc;  // 147456
    const float* lkbase = g_proj + (size_t)((0 * Bc + b) * Hc + h) * slab;
    const float* lvbase = g_proj + (size_t)((2 * Bc + b) * Hc + h) * slab;
    const float* rvbase = g_proj + (size_t)((3 * Bc + b) * Hc + h) * slab;
    const float* rkT    = g_rkT + (size_t)(b * Hc + h) * Nc * DKc * Nc;

    const int wA = tid >> 5;          // 0..11
    const int lA = tid & 31;          // y-lane
    const int as = tid >> 7;          // 0..2
    const int rr = tid & 127;
    const int yl = rr >> 2;           // 0..31
    const int dq = rr & 3;            // 0..3
    const int y  = yb + yl;

    float4 num[TXB];
    float  den[TXB];
#pragma unroll
    for (int t = 0; t < TXB; ++t) { num[t] = make_float4(0,0,0,0); den[t] = 0.f; }

    for (int a0 = 0; a0 < 96; a0 += ACH) {
        __syncthreads();

        for (int i = tid; i < 2 * CF4; i += 384) {
            int arr = i >= CF4;
            int j   = arr ? i - CF4 : i;
            int tx  = j / (ACH * DKc / 4);
            int k   = j - tx * (ACH * DKc / 4);
            const float* src = (arr ? lvbase : lkbase)
                             + (size_t)((x0 + tx) * 96 + a0) * DKc;
            float* dst = (arr ? lv_s : lk_s) + tx * (ACH * DKc);
            ((float4*)dst)[k] = ((const float4*)src)[k];
        }
        __syncthreads();

#pragma unroll
        for (int rep = 0; rep < 2; ++rep) {
            const int al = wA + rep * 12;
            const int a  = a0 + al;
            const float* rkp = rkT + ((size_t)a * DKc) * Nc + yb + lA;
            float ps[TXB];
            {
                float r[8];
#pragma unroll
                for (int d = 0; d < 8; ++d) r[d] = rkp[(size_t)d * Nc];
#pragma unroll
                for (int tx = 0; tx < TXB; ++tx) {
                    const float4* lp = (const float4*)(lk_s + (tx * ACH + al) * DKc);
                    float4 l0 = lp[0], l1 = lp[1];
                    ps[tx] = l0.x * r[0] + l0.y * r[1] + l0.z * r[2] + l0.w * r[3]
                           + l1.x * r[4] + l1.y * r[5] + l1.z * r[6] + l1.w * r[7];
                }
            }
            {
                float r[8];
#pragma unroll
                for (int d = 0; d < 8; ++d) r[d] = rkp[(size_t)(8 + d) * Nc];
#pragma unroll
                for (int tx = 0; tx < TXB; ++tx) {
                    const float4* lp = (const float4*)(lk_s + (tx * ACH + al) * DKc + 8);
                    float4 l2 = lp[0], l3 = lp[1];
                    float s = ps[tx]
                            + l2.x * r[0] + l2.y * r[1] + l2.z * r[2] + l2.w * r[3]
                            + l3.x * r[4] + l3.y * r[5] + l3.z * r[6] + l3.w * r[7];
                    sc_s[(tx * ACH + al) * YB + lA] = __expf(s * 0.25f);
                }
            }
        }
        __syncthreads();

#pragma unroll
        for (int j = 0; j < 8; ++j) {
            const int al = as * 8 + j;
            const int a  = a0 + al;
            float4 rv = *(const float4*)(rvbase + ((size_t)(a * 96 + y)) * DKc + dq * 4);
#pragma unroll
            for (int tx = 0; tx < TXB; ++tx) {
                float e = sc_s[(tx * ACH + al) * YB + yl];
                float4 v = *(const float4*)(lv_s + (tx * ACH + al) * DKc + dq * 4);
                num[tx].x += e * (v.x * rv.x);
                num[tx].y += e * (v.y * rv.y);
                num[tx].z += e * (v.z * rv.z);
                num[tx].w += e * (v.w * rv.w);
                den[tx]   += e;
            }
        }
    }

    __syncthreads();
#pragma unroll
    for (int step = 0; step < 3; ++step) {
        if (as == step) {
            float4* p4 = (float4*)part;
            if (step == 0) {
#pragma unroll
                for (int tx = 0; tx < TXB; ++tx) {
                    p4[(tx * YB + yl) * 4 + dq] = num[tx];
                    if (dq == 0) pden[tx * YB + yl] = den[tx];
                }
            } else {
#pragma unroll
                for (int tx = 0; tx < TXB; ++tx) {
                    float4 c = p4[(tx * YB + yl) * 4 + dq];
                    c.x += num[tx].x; c.y += num[tx].y;
                    c.z += num[tx].z; c.w += num[tx].w;
                    p4[(tx * YB + yl) * 4 + dq] = c;
                    if (dq == 0) pden[tx * YB + yl] += den[tx];
                }
            }
        }
        __syncthreads();
    }

    {
        const float4* p4 = (const float4*)part;
#pragma unroll
        for (int r = 0; r < 2; ++r) {
            int idx = tid + r * 384;
            int dqo = idx & 3;
            int cyl = (idx >> 2) & 31;
            int tx  = idx >> 7;
            float inv = 1.f / pden[tx * YB + cyl];
            float4 o = p4[idx];
            o.x *= inv; o.y *= inv; o.z *= inv; o.w *= inv;
            size_t row = (size_t)b * NNc + (size_t)(x0 + tx) * 96 + (yb + cyl);
            *(float4*)&g_attout[row * 64 + h * 16 + dqo * 4] = o;
        }
    }
}

// ---------------------------------------------------------------------------
// Kernel C: output projection.  32 rows x 64 cols per block, 128 threads.
// grid 576 (was 288) -> fixes the 2-blocks/SM latency starvation.
// ---------------------------------------------------------------------------
__global__ void __launch_bounds__(128)
out_kernel(const float* __restrict__ w_out, const float* __restrict__ b_out,
           float* __restrict__ out)
{
    __shared__ __align__(16) float w_s[64 * A_WS_STRIDE];
    __shared__ __align__(16) float st_s[32 * 64];
    __shared__ float bias_s[64];

    const int tid = threadIdx.x;
    const int rowBase = blockIdx.x * 32;

    for (int idx = tid; idx < 4096; idx += 128) {
        int p = idx >> 6, k = idx & 63;
        w_s[k * A_WS_STRIDE + p] = w_out[idx];
    }
    if (tid < 64) bias_s[tid] = b_out[tid];
    {
        const float4* src = (const float4*)(g_attout + (size_t)rowBase * 64);
        float4* dst = (float4*)st_s;
#pragma unroll
        for (int i = 0; i < 4; ++i) dst[tid + i * 128] = src[tid + i * 128];
    }
    __syncthreads();

    const int p0 = (tid & 15) * 4;
    const int r0 = (tid >> 4) * 4;

    float acc[4][4];
#pragma unroll
    for (int i = 0; i < 4; ++i)
#pragma unroll
        for (int j = 0; j < 4; ++j) acc[i][j] = 0.f;

#pragma unroll 8
    for (int k = 0; k < 64; ++k) {
        float4 wv = *(const float4*)&w_s[k * A_WS_STRIDE + p0];
#pragma unroll
        for (int i = 0; i < 4; ++i) {
            float s = st_s[(r0 + i) * 64 + k];
            acc[i][0] += s * wv.x;
            acc[i][1] += s * wv.y;
            acc[i][2] += s * wv.z;
            acc[i][3] += s * wv.w;
        }
    }

    const float4 bv = *(const float4*)&bias_s[p0];
#pragma unroll
    for (int i = 0; i < 4; ++i) {
        int row = rowBase + r0 + i;
        float4 v;
        v.x = acc[i][0] + bv.x;
        v.y = acc[i][1] + bv.y;
        v.z = acc[i][2] + bv.z;
        v.w = acc[i][3] + bv.w;
        *(float4*)&out[(size_t)row * 64 + p0] = v;
    }
}

// ---------------------------------------------------------------------------
extern "C" void kernel_launch(void* const* d_in, const int* in_sizes, int n_in,
                              void* d_out, int out_size)
{
    const float* state = (const float*)d_in[0];
    const float* w_lk = (const float*)d_in[1];
    const float* b_lk = (const float*)d_in[2];
    const float* w_rk = (const float*)d_in[3];
    const float* b_rk = (const float*)d_in[4];
    const float* w_lv = (const float*)d_in[5];
    const float* b_lv = (const float*)d_in[6];
    const float* w_rv = (const float*)d_in[7];
    const float* b_rv = (const float*)d_in[8];
    const float* w_out = (const float*)d_in[9];
    const float* b_out = (const float*)d_in[10];
    float* out = (float*)d_out;

    dim3 gridA(ROWS_TOTAL / 32, 4);
    proj_kernel<<<gridA, 128>>>(
        state, w_lk, b_lk, w_rk, b_rk, w_lv, b_lv, w_rv, b_rv);

    rkT_kernel<<<Bc * Hc * Nc, 128>>>();

    attn_kernel<<<Bc * Hc * (Nc / TXB) * (Nc / YB), 384>>>();

    out_kernel<<<ROWS_TOTAL / 32, 128>>>(w_out, b_out, out);
}